// round 11
// baseline (speedup 1.0000x reference)
#include <cuda_runtime.h>
#include <cstdint>

#define T_STEPS 256
#define BATCH   128
#define KDIM    1536
#define F4      384     // KDIM/4 (float4 units)
#define NTHR    256     // 2 groups x 128 threads
#define STAGES  3
#define STAGE_B 6144u   // F4 * 16 bytes

// HW tanh: single MUFU op, max rel err ~2^-11.
__device__ __forceinline__ float tanha(float x) {
    float y;
    asm("tanh.approx.f32 %0, %1;" : "=f"(y) : "f"(x));
    return y;
}

__device__ __forceinline__ void cp_async16(uint32_t dst, const void* src) {
    asm volatile("cp.async.cg.shared.global [%0], [%1], 16;" :: "r"(dst), "l"(src));
}
#define CP_COMMIT() asm volatile("cp.async.commit_group;" ::: "memory")
#define CP_WAIT2()  asm volatile("cp.async.wait_group 2;" ::: "memory")
// per-group named barrier (128 threads each; ids 1 and 2)
#define GBAR() asm volatile("bar.sync %0, 128;" :: "r"(barid) : "memory")

// packed f32x2 fma
__device__ __forceinline__ void ffma2(unsigned long long& acc,
                                      unsigned long long a,
                                      unsigned long long b) {
    asm("fma.rn.f32x2 %0, %1, %2, %0;" : "+l"(acc) : "l"(a), "l"(b));
}
__device__ __forceinline__ float2 unpack2(unsigned long long v) {
    float2 f;
    asm("mov.b64 {%0, %1}, %2;" : "=f"(f.x), "=f"(f.y) : "l"(v));
    return f;
}

// 12-term dot product (3 float4 each side), 2 accumulator chains.
__device__ __forceinline__ float dot12(const float4* v, const float4* w) {
    float a0 = 0.0f, a1 = 0.0f;
    #pragma unroll
    for (int j = 0; j < 3; j++) {
        a0 = fmaf(v[j].x, w[j].x, fmaf(v[j].y, w[j].y, a0));
        a1 = fmaf(v[j].z, w[j].z, fmaf(v[j].w, w[j].w, a1));
    }
    return a0 + a1;
}

// ---------------------------------------------------------------------------
// Two independent recurrences per CTA: 256 threads = 2 groups x 128.
// Group g handles batch (2*blockIdx.x + g) with its own named barrier and
// its own 3-stage cp.async input ring, so each SMSP carries TWO warps from
// INDEPENDENT serial chains — chain A's SHFL/MUFU/barrier latency is hidden
// by chain B's issue stream. Within a group: strided float4 ownership
// (gtid + 128*j), 6-sum warp butterfly (4 gates of t + 2 input sums of t+1,
// x-dots in FFMA2), one named barrier, 4-wide tail, 6 broadcasts,
// tanh.approx update. Loop unrolled by 6 (stage ring x buffer parity).
// ---------------------------------------------------------------------------
__global__ void __launch_bounds__(NTHR) fused_kernel(
    const float* __restrict__ inputs,
    const float* __restrict__ h0,
    const float* __restrict__ c0,
    const float* __restrict__ Wr,
    const float* __restrict__ br,
    const float* __restrict__ Wc,
    const float* __restrict__ bc,
    const float* __restrict__ Wi,
    const float* __restrict__ bi,
    float* __restrict__ out)
{
    __shared__ float      sPart[2][2][8][4];   // [group][buf][row][warp]
    __shared__ ulonglong2 sX[2][STAGES * F4];  // [group][3 x 6KB stages]

    const int tid   = threadIdx.x;
    const int group = tid >> 7;
    const int gtid  = tid & 127;
    const int b     = blockIdx.x * 2 + group;
    const int warp  = gtid >> 5;
    const int lane  = tid & 31;
    const int barid = group + 1;

    const float4*     in4 = (const float4*)inputs;
    const float4*     Wr4 = (const float4*)Wr;
    const float4*     Wc4 = (const float4*)Wc;
    const ulonglong2* Wi2 = (const ulonglong2*)Wi;
    float4* out4 = (float4*)out;

    float4 h[3], c[3], wr0[3], wr1[3], wc0[3], wc1[3];
    ulonglong2 wi0p[3], wi1p[3];
    #pragma unroll
    for (int j = 0; j < 3; j++) {
        const int p = gtid + 128 * j;          // strided ownership: coalesced
        h[j]    = ((const float4*)h0)[b * F4 + p];
        c[j]    = ((const float4*)c0)[b * F4 + p];
        wr0[j]  = Wr4[p];        wr1[j]  = Wr4[F4 + p];
        wc0[j]  = Wc4[p];        wc1[j]  = Wc4[F4 + p];
        wi0p[j] = Wi2[p];        wi1p[j] = Wi2[F4 + p];
    }
    const float br0 = br[0], br1 = br[1];
    const float bc0 = bc[0], bc1 = bc[1];
    const float bi0 = bi[0], bi1 = bi[1];

    const int rid = lane & 7;
    const float mybias = (rid == 0) ? br0 : (rid == 1) ? br1
                       : (rid == 2) ? bc0 : (rid == 3) ? bc1
                       : (rid == 4) ? bi0 : (rid == 5) ? bi1 : 0.0f;

    // lane roles for the 6-sum butterfly
    const bool lo  = lane < 16;
    const bool b3  = (lane & 8) != 0;
    const bool b2  = (lane & 4) != 0;
    const bool writer = lo ? ((lane & 3) == 0) : ((lane & 7) == 0);
    const int  wrow   = lo ? (((lane >> 3) & 1) * 2 + ((lane >> 2) & 1))
                           : (4 + ((lane >> 3) & 1));

    // zero unused tail rows (6,7) in both buffers (per group)
    if (gtid < 16) {
        const int bf = gtid >> 3, r = 6 + ((gtid >> 2) & 1), col = gtid & 3;
        sPart[group][bf][r][col] = 0.0f;
    }

    const uint32_t sx_tid =
        (uint32_t)__cvta_generic_to_shared(&sX[group][0]) + (uint32_t)gtid * 16u;
    const ulonglong2* sXu = &sX[group][0];

    // ---- prologue: X0 projection; fill stages 1,2,0 with x_1,x_2,x_3 ----
    {
        float4 x0[3];
        #pragma unroll
        for (int j = 0; j < 3; j++)
            x0[j] = in4[(long)b * F4 + gtid + 128 * j];
        float4 wi0f[3], wi1f[3];
        #pragma unroll
        for (int j = 0; j < 3; j++) {
            wi0f[j] = *(const float4*)&wi0p[j];
            wi1f[j] = *(const float4*)&wi1p[j];
        }
        float v4 = dot12(x0, wi0f);
        float v5 = dot12(x0, wi1f);

        #pragma unroll
        for (int s = 1; s <= 3; s++) {
            const float4* src = in4 + (long)s * BATCH * F4 + (long)b * F4 + gtid;
            const uint32_t dst = sx_tid + (uint32_t)(s % STAGES) * STAGE_B;
            cp_async16(dst,         src);
            cp_async16(dst + 2048u, src + 128);
            cp_async16(dst + 4096u, src + 256);
            CP_COMMIT();
        }

        float k  = lo ? v4 : v5;
        float s_ = lo ? v5 : v4;
        k += __shfl_xor_sync(~0u, s_, 16);
        k += __shfl_xor_sync(~0u, k, 8);
        k += __shfl_xor_sync(~0u, k, 4);
        k += __shfl_xor_sync(~0u, k, 2);
        k += __shfl_xor_sync(~0u, k, 1);
        if (lane == 0)  sPart[group][1][4][warp] = k;
        if (lane == 16) sPart[group][1][5][warp] = k;
    }
    GBAR();
    float Xc, Xh;
    {
        float4 q4 = *(const float4*)sPart[group][1][4];
        float4 q5 = *(const float4*)sPart[group][1][5];
        Xc = (q4.x + q4.y) + (q4.z + q4.w) + bi0;
        Xh = (q5.x + q5.y) + (q5.z + q5.w) + bi1;
    }

    // strength-reduced pointers
    const float4* srcp = in4 + (long)4 * BATCH * F4 + (long)b * F4 + gtid; // x_{t+4}
    float4*       outp = out4 + (long)b * F4 + gtid;

#define DO_STEP(SC, BUF, SRC)                                                  \
    {                                                                          \
        CP_WAIT2();                                                            \
        const ulonglong2* xs = sXu + (SC) * F4 + gtid;                         \
        ulonglong2 x0 = xs[0], x1 = xs[128], x2 = xs[256];                     \
        {   /* refill consumed stage SC with x from SRC */                     \
            const uint32_t dst = sx_tid + (uint32_t)(SC) * STAGE_B;            \
            cp_async16(dst,         (SRC));                                    \
            cp_async16(dst + 2048u, (SRC) + 128);                              \
            cp_async16(dst + 4096u, (SRC) + 256);                              \
            CP_COMMIT();                                                       \
        }                                                                      \
        /* x-projection dots for t+1: packed FFMA2 */                          \
        unsigned long long a0 = 0ull, a1 = 0ull, q0_ = 0ull, q1_ = 0ull;       \
        ffma2(a0, x0.x, wi0p[0].x); ffma2(a1, x0.y, wi0p[0].y);                \
        ffma2(q0_, x0.x, wi1p[0].x); ffma2(q1_, x0.y, wi1p[0].y);              \
        ffma2(a0, x1.x, wi0p[1].x); ffma2(a1, x1.y, wi0p[1].y);                \
        ffma2(q0_, x1.x, wi1p[1].x); ffma2(q1_, x1.y, wi1p[1].y);              \
        ffma2(a0, x2.x, wi0p[2].x); ffma2(a1, x2.y, wi0p[2].y);                \
        ffma2(q0_, x2.x, wi1p[2].x); ffma2(q1_, x2.y, wi1p[2].y);              \
        float2 pa0 = unpack2(a0), pa1 = unpack2(a1);                           \
        float2 pb0 = unpack2(q0_), pb1 = unpack2(q1_);                         \
        float x4 = (pa0.x + pa0.y) + (pa1.x + pa1.y);                          \
        float x5 = (pb0.x + pb0.y) + (pb1.x + pb1.y);                          \
        /* gate dots */                                                        \
        float g0 = dot12(h, wr0), g1 = dot12(h, wr1);                          \
        float g2 = dot12(c, wc0), g3 = dot12(c, wc1);                          \
        /* 6-sum butterfly: 9 SHFL, 5 levels */                                \
        float rA = __shfl_xor_sync(~0u, lo ? x4 : g0, 16);                     \
        float rB = __shfl_xor_sync(~0u, lo ? x5 : g1, 16);                     \
        float rC = __shfl_xor_sync(~0u, g2, 16);                               \
        float rD = __shfl_xor_sync(~0u, g3, 16);                               \
        if (lo) { g0 += rA; g1 += rB; g2 += rC; g3 += rD; }                    \
        else    { x4 += rA; x5 += rB; }                                        \
        float P  = lo ? (b3 ? g2 : g0) : (b3 ? x5 : x4);                       \
        float sP = lo ? (b3 ? g0 : g2) : (b3 ? x4 : x5);                       \
        P += __shfl_xor_sync(~0u, sP, 8);                                      \
        float Q  = b3 ? g3 : g1;                                               \
        float sQ = b3 ? g1 : g3;                                               \
        Q += __shfl_xor_sync(~0u, sQ, 8);                                      \
        float R  = lo ? (b2 ? Q : P) : P;                                      \
        float sR = lo ? (b2 ? P : Q) : P;                                      \
        R += __shfl_xor_sync(~0u, sR, 4);                                      \
        R += __shfl_xor_sync(~0u, R, 2);                                       \
        R += __shfl_xor_sync(~0u, R, 1);                                       \
        if (writer) sPart[group][BUF][wrow][warp] = R;                         \
        GBAR();                                                                \
        float4 qv = *(const float4*)sPart[group][BUF][rid];                    \
        float s = (qv.x + qv.y) + (qv.z + qv.w) + mybias;                      \
        float gval;                                                            \
        if (rid < 4) {                                                         \
            float sg  = fmaf(-0.5f, tanha(0.5f * s), 0.5f);                    \
            float fac = (rid == 0) ? Xc : (rid == 3) ? Xh : 1.0f;              \
            gval = sg * fac;                                                   \
        } else {                                                               \
            gval = s;                                                          \
        }                                                                      \
        const float gca = __shfl_sync(~0u, gval, 0);                           \
        const float ghb = __shfl_sync(~0u, gval, 1);                           \
        const float gcb = __shfl_sync(~0u, gval, 2);                           \
        const float gha = __shfl_sync(~0u, gval, 3);                           \
        Xc = __shfl_sync(~0u, gval, 4);                                        \
        Xh = __shfl_sync(~0u, gval, 5);                                        \
        _Pragma("unroll")                                                      \
        for (int j = 0; j < 3; j++) {                                          \
            h[j].x = tanha(fmaf(ghb, h[j].x, gha));                            \
            h[j].y = tanha(fmaf(ghb, h[j].y, gha));                            \
            h[j].z = tanha(fmaf(ghb, h[j].z, gha));                            \
            h[j].w = tanha(fmaf(ghb, h[j].w, gha));                            \
            c[j].x = tanha(fmaf(gcb, c[j].x, gca));                            \
            c[j].y = tanha(fmaf(gcb, c[j].y, gca));                            \
            c[j].z = tanha(fmaf(gcb, c[j].z, gca));                            \
            c[j].w = tanha(fmaf(gcb, c[j].w, gca));                            \
            outp[128 * j] = h[j];                                              \
        }                                                                      \
        outp += BATCH * F4;                                                    \
    }

    // main loop: 252 steps, unrolled by 6 (stage ring period 3 x parity 2)
    for (int i = 0; i < 42; i++) {
        DO_STEP(1, 0, srcp); srcp += BATCH * F4;
        DO_STEP(2, 1, srcp); srcp += BATCH * F4;
        DO_STEP(0, 0, srcp); srcp += BATCH * F4;
        DO_STEP(1, 1, srcp); srcp += BATCH * F4;
        DO_STEP(2, 0, srcp); srcp += BATCH * F4;
        DO_STEP(0, 1, srcp); srcp += BATCH * F4;
    }
    // tail: steps 252..255, refill source clamped to x_255
    {
        const float4* srcL = in4 + (long)(T_STEPS - 1) * BATCH * F4
                           + (long)b * F4 + gtid;
        DO_STEP(1, 0, srcL);
        DO_STEP(2, 1, srcL);
        DO_STEP(0, 0, srcL);
        DO_STEP(1, 1, srcL);
    }
#undef DO_STEP

    // final hT, cT
    const long offH = (long)T_STEPS * BATCH * F4;
    const long offC = offH + (long)BATCH * F4;
    #pragma unroll
    for (int j = 0; j < 3; j++) {
        out4[offH + (long)b * F4 + gtid + 128 * j] = h[j];
        out4[offC + (long)b * F4 + gtid + 128 * j] = c[j];
    }
}

extern "C" void kernel_launch(void* const* d_in, const int* in_sizes, int n_in,
                              void* d_out, int out_size)
{
    const float* inputs = (const float*)d_in[0];
    const float* h0     = (const float*)d_in[1];
    const float* c0     = (const float*)d_in[2];
    const float* Wr     = (const float*)d_in[3];
    const float* br     = (const float*)d_in[4];
    const float* Wc     = (const float*)d_in[5];
    const float* bc     = (const float*)d_in[6];
    const float* Wi     = (const float*)d_in[7];
    const float* bi     = (const float*)d_in[8];
    float* out = (float*)d_out;

    fused_kernel<<<BATCH / 2, NTHR>>>(inputs, h0, c0, Wr, br, Wc, bc, Wi, bi, out);
}